// round 3
// baseline (speedup 1.0000x reference)
#include <cuda_runtime.h>
#include <math.h>

#define B_    64
#define F_    1024
#define HID_  2048
#define NH_   4
#define KS_   4
#define HD_   512
#define EPS_  1e-6f
#define KSC   0.044194173824159216f   // 1/sqrt(512)

// ---- output layout (float count offsets) ----
#define OUT_Y   0
#define OUT_C   (B_*F_)                              // 65536
#define OUT_N   (OUT_C + B_*NH_*HD_*HD_)             // 67174400
#define OUT_M   (OUT_N + B_*NH_*HD_)                 // 67305472
#define OUT_CS  (OUT_M + B_*NH_)                     // 67305728

// ---- scratch ----
__device__ __align__(16) float g_up[B_ * 2 * HID_];
__device__ __align__(16) float g_convact[B_ * HID_];
__device__ __align__(16) float g_q[B_ * HID_];
__device__ __align__(16) float g_k[B_ * HID_];      // UNSCALED k
__device__ __align__(16) float g_v[B_ * HID_];
__device__ float g_fp[B_ * NH_];
__device__ float g_ip[B_ * NH_];
__device__ float g_den[B_ * NH_];
__device__ __align__(16) float g_nom[B_ * NH_ * HD_];
__device__ __align__(16) float g_h[B_ * HID_];

__device__ __forceinline__ float warpsum(float v) {
#pragma unroll
    for (int o = 16; o; o >>= 1) v += __shfl_down_sync(0xffffffffu, v, o);
    return v;
}

__device__ __forceinline__ float4 warpsum4(float4 v) {
#pragma unroll
    for (int o = 16; o; o >>= 1) {
        v.x += __shfl_down_sync(0xffffffffu, v.x, o);
        v.y += __shfl_down_sync(0xffffffffu, v.y, o);
        v.z += __shfl_down_sync(0xffffffffu, v.z, o);
        v.w += __shfl_down_sync(0xffffffffu, v.w, o);
    }
    return v;
}

__device__ __forceinline__ float siluf(float s) { return s / (1.f + expf(-s)); }

// ============================================================
// K1: up = inputs @ W_up  (64 x 1024 x 4096), NO split-K.
// grid 128 (N tiles of 32), block 256, plain stores.
// ============================================================
__global__ void __launch_bounds__(256) gemm_up_kernel(
        const float* __restrict__ A, const float* __restrict__ Bm) {
    const int K = F_, N = 2 * HID_;
    const int n0 = blockIdx.x * 32;
    const int tid = threadIdx.x;
    const int tx = tid & 7, ty = tid >> 3;   // 8 x 32

    __shared__ float As[16][65];
    __shared__ float Bs[16][32];

    float acc[2][4] = {};

    for (int kt = 0; kt < K; kt += 16) {
        __syncthreads();
#pragma unroll
        for (int i = 0; i < 4; i++) {
            int lin = tid + i * 256;
            int mm = lin >> 4, kk = lin & 15;
            As[kk][mm] = A[mm * K + kt + kk];
        }
        {
            int lin = tid;                       // 512 loads by first 512... block=256, do 2
#pragma unroll
            for (int i = 0; i < 2; i++) {
                int l2 = lin + i * 256;
                int kk2 = l2 >> 5, jj = l2 & 31;
                Bs[kk2][jj] = Bm[(size_t)(kt + kk2) * N + n0 + jj];
            }
        }
        __syncthreads();
#pragma unroll
        for (int kk = 0; kk < 16; kk++) {
            float4 b4 = *(const float4*)&Bs[kk][tx * 4];
            float a0 = As[kk][ty * 2 + 0];
            float a1 = As[kk][ty * 2 + 1];
            acc[0][0] += a0 * b4.x; acc[0][1] += a0 * b4.y; acc[0][2] += a0 * b4.z; acc[0][3] += a0 * b4.w;
            acc[1][0] += a1 * b4.x; acc[1][1] += a1 * b4.y; acc[1][2] += a1 * b4.z; acc[1][3] += a1 * b4.w;
        }
    }
#pragma unroll
    for (int i = 0; i < 2; i++) {
        float4 r = make_float4(acc[i][0], acc[i][1], acc[i][2], acc[i][3]);
        *(float4*)&g_up[(size_t)(ty * 2 + i) * N + n0 + tx * 4] = r;
    }
}

// ============================================================
// K2: FUSED conv + silu + block-diag qkv + gates + n_new/den.
// grid 64 (one per batch), block 512 (one thread per 4-ch block).
// Also writes conv_state_new, m_new, n_new to out; zeroes g_nom.
// ============================================================
__global__ void __launch_bounds__(512) fused_mid_kernel(
        const float* __restrict__ cs_in,
        const float* __restrict__ conv_w, const float* __restrict__ conv_b,
        const float* __restrict__ Wq, const float* __restrict__ Wk,
        const float* __restrict__ Wv,
        const float* __restrict__ nst, const float* __restrict__ mst,
        const float* __restrict__ Wi, const float* __restrict__ bi,
        const float* __restrict__ Wf, const float* __restrict__ bf,
        float* __restrict__ out) {
    const int b = blockIdx.x;
    const int nb = threadIdx.x;         // 0..511
    const int ch0 = nb * 4;
    const int lane = nb & 31, wid = nb >> 5;   // 16 warps

    // ---- conv + conv_state_new ----
    const float* csb = cs_in + (size_t)b * KS_ * HID_;
    float4 c0 = *(const float4*)&csb[1 * HID_ + ch0];
    float4 c1 = *(const float4*)&csb[2 * HID_ + ch0];
    float4 c2 = *(const float4*)&csb[3 * HID_ + ch0];
    float4 xv = *(const float4*)&g_up[b * 4096 + ch0];

    float* ocs = out + OUT_CS + (size_t)b * KS_ * HID_;
    *(float4*)&ocs[0 * HID_ + ch0] = c0;
    *(float4*)&ocs[1 * HID_ + ch0] = c1;
    *(float4*)&ocs[2 * HID_ + ch0] = c2;
    *(float4*)&ocs[3 * HID_ + ch0] = xv;

    float4 w0 = *(const float4*)&conv_w[0 * HID_ + ch0];
    float4 w1 = *(const float4*)&conv_w[1 * HID_ + ch0];
    float4 w2 = *(const float4*)&conv_w[2 * HID_ + ch0];
    float4 w3 = *(const float4*)&conv_w[3 * HID_ + ch0];
    float4 cb = *(const float4*)&conv_b[ch0];

    float4 s;
    s.x = c0.x * w0.x + c1.x * w1.x + c2.x * w2.x + xv.x * w3.x + cb.x;
    s.y = c0.y * w0.y + c1.y * w1.y + c2.y * w2.y + xv.y * w3.y + cb.y;
    s.z = c0.z * w0.z + c1.z * w1.z + c2.z * w2.z + xv.z * w3.z + cb.z;
    s.w = c0.w * w0.w + c1.w * w1.w + c2.w * w2.w + xv.w * w3.w + cb.w;
    float4 act = make_float4(siluf(s.x), siluf(s.y), siluf(s.z), siluf(s.w));
    *(float4*)&g_convact[b * 2048 + ch0] = act;

    // ---- block-diagonal qkv (4x4 per block) ----
    const float4* wqv = (const float4*)(Wq + nb * 16);   // rows d=0..3, e contiguous
    const float4* wkv = (const float4*)(Wk + nb * 16);
    const float4* wvv = (const float4*)(Wv + nb * 16);
    float4 q4 = make_float4(0, 0, 0, 0), k4 = q4, v4 = q4;
    {
        float ad[4] = {act.x, act.y, act.z, act.w};
        float xd[4] = {xv.x, xv.y, xv.z, xv.w};
#pragma unroll
        for (int d = 0; d < 4; d++) {
            float4 wq = wqv[d], wk = wkv[d], wv = wvv[d];
            q4.x += ad[d] * wq.x; q4.y += ad[d] * wq.y; q4.z += ad[d] * wq.z; q4.w += ad[d] * wq.w;
            k4.x += ad[d] * wk.x; k4.y += ad[d] * wk.y; k4.z += ad[d] * wk.z; k4.w += ad[d] * wk.w;
            v4.x += xd[d] * wv.x; v4.y += xd[d] * wv.y; v4.z += xd[d] * wv.z; v4.w += xd[d] * wv.w;
        }
    }
    *(float4*)&g_q[b * 2048 + ch0] = q4;
    *(float4*)&g_k[b * 2048 + ch0] = k4;
    *(float4*)&g_v[b * 2048 + ch0] = v4;

    // ---- gate pre-activations: ai[h], af[h] (h=0..3 packed in float4) ----
    float4 ai = make_float4(0, 0, 0, 0), af = ai;
    {
        const float4* WiV = (const float4*)Wi;   // row j -> float4 over h
        const float4* WfV = (const float4*)Wf;
        float qa[4] = {q4.x, q4.y, q4.z, q4.w};
        float ka[4] = {k4.x, k4.y, k4.z, k4.w};
        float va[4] = {v4.x, v4.y, v4.z, v4.w};
#pragma unroll
        for (int e = 0; e < 4; e++) {
            float4 wi = WiV[ch0 + e], wf = WfV[ch0 + e];
            ai.x += qa[e] * wi.x; ai.y += qa[e] * wi.y; ai.z += qa[e] * wi.z; ai.w += qa[e] * wi.w;
            af.x += qa[e] * wf.x; af.y += qa[e] * wf.y; af.z += qa[e] * wf.z; af.w += qa[e] * wf.w;
        }
#pragma unroll
        for (int e = 0; e < 4; e++) {
            float4 wi = WiV[2048 + ch0 + e], wf = WfV[2048 + ch0 + e];
            ai.x += ka[e] * wi.x; ai.y += ka[e] * wi.y; ai.z += ka[e] * wi.z; ai.w += ka[e] * wi.w;
            af.x += ka[e] * wf.x; af.y += ka[e] * wf.y; af.z += ka[e] * wf.z; af.w += ka[e] * wf.w;
        }
#pragma unroll
        for (int e = 0; e < 4; e++) {
            float4 wi = WiV[4096 + ch0 + e], wf = WfV[4096 + ch0 + e];
            ai.x += va[e] * wi.x; ai.y += va[e] * wi.y; ai.z += va[e] * wi.z; ai.w += va[e] * wi.w;
            af.x += va[e] * wf.x; af.y += va[e] * wf.y; af.z += va[e] * wf.z; af.w += va[e] * wf.w;
        }
    }

    __shared__ float4 sai[16], saf[16];
    __shared__ float sfp[4], sip[4], smn[4];
    __shared__ float dred[16];

    ai = warpsum4(ai); af = warpsum4(af);
    if (lane == 0) { sai[wid] = ai; saf[wid] = af; }
    __syncthreads();

    if (nb < 4) {
        int h = nb;
        float ti = 0.f, tf = 0.f;
#pragma unroll
        for (int w = 0; w < 16; w++) {
            float4 a = sai[w], f = saf[w];
            ti += (h == 0) ? a.x : (h == 1) ? a.y : (h == 2) ? a.z : a.w;
            tf += (h == 0) ? f.x : (h == 1) ? f.y : (h == 2) ? f.z : f.w;
        }
        float it = ti + bi[h];
        float ft = tf + bf[h];
        float logf_ = -(fmaxf(-ft, 0.f) + log1pf(expf(-fabsf(ft))));
        float mold = mst[b * 4 + h];
        float mnew = fmaxf(logf_ + mold, it);
        float ip = expf(it - mnew);
        float fp = expf(logf_ + mold - mnew);
        out[OUT_M + b * 4 + h] = mnew;
        g_fp[b * 4 + h] = fp; g_ip[b * 4 + h] = ip;
        sfp[h] = fp; sip[h] = ip; smn[h] = mnew;
    }
    __syncthreads();

    // ---- n_new, den partial; zero g_nom slice ----
    const int h = nb >> 7;                    // 128 threads per head
    float fp = sfp[h], ip = sip[h];
    float4 nold = *(const float4*)&nst[b * 2048 + ch0];
    float4 nn;
    nn.x = fp * nold.x + ip * KSC * k4.x;
    nn.y = fp * nold.y + ip * KSC * k4.y;
    nn.z = fp * nold.z + ip * KSC * k4.z;
    nn.w = fp * nold.w + ip * KSC * k4.w;
    *(float4*)&(out + OUT_N)[b * 2048 + ch0] = nn;
    *(float4*)&g_nom[b * 2048 + ch0] = make_float4(0, 0, 0, 0);

    float dacc = q4.x * nn.x + q4.y * nn.y + q4.z * nn.z + q4.w * nn.w;
    dacc = warpsum(dacc);                      // each warp is single-head (4 warps/head)
    if (lane == 0) dred[wid] = dacc;
    __syncthreads();
    if (nb < 4) {
        float ssum = dred[nb * 4] + dred[nb * 4 + 1] + dred[nb * 4 + 2] + dred[nb * 4 + 3];
        float den = fmaxf(fabsf(ssum), expf(-smn[nb])) + EPS_;
        g_den[b * 4 + nb] = den;
    }
}

// ============================================================
// K3: C_new = fp*C + ip*kh (x) vh fused with nom = q^T C_new.
// Streaming loads/stores (no reuse of C).
// grid (4, 256), block 256.
// ============================================================
__global__ void __launch_bounds__(256) cupdate_kernel(
        const float* __restrict__ Cin, float* __restrict__ out) {
    int bh = blockIdx.y;
    int b = bh >> 2, h = bh & 3;
    int tid = threadIdx.x;
    int ty = tid >> 7;
    int tx = tid & 127;
    int e0 = tx * 4;
    int d0 = blockIdx.x * 128 + ty * 64;

    float fp = g_fp[bh], ip = g_ip[bh];

    __shared__ float sa[2][64], sq[2][64];
    if (tx < 64) {
        int gd = b * 2048 + h * 512 + d0 + tx;
        sa[ty][tx] = ip * KSC * g_k[gd];
        sq[ty][tx] = g_q[gd];
    }
    __syncthreads();

    float4 vh = *(const float4*)&g_v[b * 2048 + h * 512 + e0];

    const float4* cbase = (const float4*)(Cin + ((size_t)bh * 512 + d0) * 512 + e0);
    float4* obase = (float4*)(out + OUT_C + ((size_t)bh * 512 + d0) * 512 + e0);

    float4 nom = make_float4(0.f, 0.f, 0.f, 0.f);
#pragma unroll 8
    for (int dd = 0; dd < 64; dd++) {
        float a  = sa[ty][dd];
        float qd = sq[ty][dd];
        float4 c = __ldcs(cbase + (size_t)dd * 128);
        float4 cn;
        cn.x = fp * c.x + a * vh.x;
        cn.y = fp * c.y + a * vh.y;
        cn.z = fp * c.z + a * vh.z;
        cn.w = fp * c.w + a * vh.w;
        __stcs(obase + (size_t)dd * 128, cn);
        nom.x += qd * cn.x;
        nom.y += qd * cn.y;
        nom.z += qd * cn.z;
        nom.w += qd * cn.w;
    }
    float* np = &g_nom[bh * 512 + e0];
    atomicAdd(np + 0, nom.x);
    atomicAdd(np + 1, nom.y);
    atomicAdd(np + 2, nom.z);
    atomicAdd(np + 3, nom.w);
}

// ============================================================
// K4: h_tilde = nom/den, layernorm, skip, silu(z) gate; zero y.
// grid 256 x 256
// ============================================================
__global__ void __launch_bounds__(256) finalize_kernel(
        const float* __restrict__ norm_scale, const float* __restrict__ skip,
        float* __restrict__ out) {
    int bh = blockIdx.x;
    int b = bh >> 2, h = bh & 3;
    int tid = threadIdx.x;
    int lane = tid & 31, wid = tid >> 5;

    out[OUT_Y + bh * 256 + tid] = 0.f;

    float den = g_den[bh];
    float v0 = g_nom[bh * 512 + tid] / den;
    float v1 = g_nom[bh * 512 + tid + 256] / den;

    float s = v0 + v1;
    float ss = v0 * v0 + v1 * v1;
    s = warpsum(s); ss = warpsum(ss);
    __shared__ float r1[8], r2[8], st[2];
    if (lane == 0) { r1[wid] = s; r2[wid] = ss; }
    __syncthreads();
    if (tid == 0) {
        float ts = 0.f, tss = 0.f;
#pragma unroll
        for (int w = 0; w < 8; w++) { ts += r1[w]; tss += r2[w]; }
        float mu = ts / 512.f;
        float var = tss / 512.f - mu * mu;
        st[0] = mu;
        st[1] = rsqrtf(var + EPS_);
    }
    __syncthreads();
    float mu = st[0], rstd = st[1];

#pragma unroll
    for (int i = 0; i < 2; i++) {
        int e = tid + i * 256;
        int hid = h * 512 + e;
        float v = (i == 0) ? v0 : v1;
        float hn = (v - mu) * rstd * norm_scale[h * 512 + e];
        float hv = hn + skip[hid] * g_convact[b * 2048 + hid];
        float z = g_up[b * 4096 + 2048 + hid];
        g_h[b * 2048 + hid] = hv * siluf(z);
    }
}

// ============================================================
// K5: y = g_h @ W_down (64x2048x1024), split-K=8, atomics.
// ============================================================
__global__ void __launch_bounds__(256) gemm_down_kernel(
        const float* __restrict__ Wd, float* __restrict__ out, int KC) {
    const float* A = g_h;
    const int K = HID_, N = F_;
    const int n0 = blockIdx.x * 64;
    const int k0 = blockIdx.y * KC;
    const int tid = threadIdx.x;
    const int tx = tid & 15, ty = tid >> 4;
    __shared__ float As[16][65];
    __shared__ float Bs[16][64];
    float acc[4][4] = {};
    for (int kt = 0; kt < KC; kt += 16) {
        __syncthreads();
#pragma unroll
        for (int i = 0; i < 4; i++) {
            int lin = tid + i * 256;
            int mm = lin >> 4, kk = lin & 15;
            As[kk][mm] = A[mm * K + k0 + kt + kk];
            int kk2 = lin >> 6, jj = lin & 63;
            Bs[kk2][jj] = Wd[(size_t)(k0 + kt + kk2) * N + n0 + jj];
        }
        __syncthreads();
#pragma unroll
        for (int kk = 0; kk < 16; kk++) {
            float4 b4 = *(const float4*)&Bs[kk][tx * 4];
            float a0 = As[kk][ty * 4 + 0];
            float a1 = As[kk][ty * 4 + 1];
            float a2 = As[kk][ty * 4 + 2];
            float a3 = As[kk][ty * 4 + 3];
            acc[0][0] += a0 * b4.x; acc[0][1] += a0 * b4.y; acc[0][2] += a0 * b4.z; acc[0][3] += a0 * b4.w;
            acc[1][0] += a1 * b4.x; acc[1][1] += a1 * b4.y; acc[1][2] += a1 * b4.z; acc[1][3] += a1 * b4.w;
            acc[2][0] += a2 * b4.x; acc[2][1] += a2 * b4.y; acc[2][2] += a2 * b4.z; acc[2][3] += a2 * b4.w;
            acc[3][0] += a3 * b4.x; acc[3][1] += a3 * b4.y; acc[3][2] += a3 * b4.z; acc[3][3] += a3 * b4.w;
        }
    }
#pragma unroll
    for (int i = 0; i < 4; i++) {
        float* crow = out + OUT_Y + (size_t)(ty * 4 + i) * N + n0 + tx * 4;
        atomicAdd(crow + 0, acc[i][0]);
        atomicAdd(crow + 1, acc[i][1]);
        atomicAdd(crow + 2, acc[i][2]);
        atomicAdd(crow + 3, acc[i][3]);
    }
}

extern "C" void kernel_launch(void* const* d_in, const int* in_sizes, int n_in,
                              void* d_out, int out_size) {
    const float* inputs     = (const float*)d_in[0];
    const float* C          = (const float*)d_in[1];
    const float* n_state    = (const float*)d_in[2];
    const float* m_state    = (const float*)d_in[3];
    const float* conv_state = (const float*)d_in[4];
    const float* W_up       = (const float*)d_in[5];
    const float* conv_w     = (const float*)d_in[6];
    const float* conv_b     = (const float*)d_in[7];
    const float* Wq         = (const float*)d_in[8];
    const float* Wk         = (const float*)d_in[9];
    const float* Wv         = (const float*)d_in[10];
    const float* Wi         = (const float*)d_in[11];
    const float* bi         = (const float*)d_in[12];
    const float* Wf         = (const float*)d_in[13];
    const float* bf         = (const float*)d_in[14];
    const float* norm_scale = (const float*)d_in[15];
    const float* skip       = (const float*)d_in[16];
    const float* W_down     = (const float*)d_in[17];
    float* out = (float*)d_out;

    // K1: up projection (no split-K, no zero)
    gemm_up_kernel<<<128, 256>>>(inputs, W_up);

    // K2: fused conv/qkv/gates/n_new/den (+conv_state_new, m_new, n_new out)
    fused_mid_kernel<<<64, 512>>>(conv_state, conv_w, conv_b, Wq, Wk, Wv,
                                  n_state, m_state, Wi, bi, Wf, bf, out);

    // K3: C update fused with q^T C_new
    cupdate_kernel<<<dim3(4, 256), 256>>>(C, out);

    // K4: layernorm epilogue; zero y
    finalize_kernel<<<256, 256>>>(norm_scale, skip, out);

    // K5: down projection, split-K=8
    gemm_down_kernel<<<dim3(16, 8), 256>>>(W_down, out, 256);
}

// round 5
// speedup vs baseline: 1.2988x; 1.2988x over previous
#include <cuda_runtime.h>
#include <math.h>

#define B_    64
#define F_    1024
#define HID_  2048
#define NH_   4
#define KS_   4
#define HD_   512
#define EPS_  1e-6f
#define KSC   0.044194173824159216f   // 1/sqrt(512)

// ---- output layout (float count offsets) ----
#define OUT_Y   0
#define OUT_C   (B_*F_)                              // 65536
#define OUT_N   (OUT_C + B_*NH_*HD_*HD_)             // 67174400
#define OUT_M   (OUT_N + B_*NH_*HD_)                 // 67305472
#define OUT_CS  (OUT_M + B_*NH_)                     // 67305728

// ---- scratch ----
__device__ __align__(16) float g_up[B_ * 2 * HID_];
__device__ __align__(16) float g_convact[B_ * HID_];
__device__ __align__(16) float g_q[B_ * HID_];
__device__ __align__(16) float g_k[B_ * HID_];      // UNSCALED k
__device__ __align__(16) float g_v[B_ * HID_];
__device__ float g_fp[B_ * NH_];
__device__ float g_ip[B_ * NH_];
__device__ float g_den[B_ * NH_];
__device__ __align__(16) float g_nom[B_ * NH_ * HD_];
__device__ __align__(16) float g_h[B_ * HID_];

__device__ __forceinline__ float warpsum(float v) {
#pragma unroll
    for (int o = 16; o; o >>= 1) v += __shfl_down_sync(0xffffffffu, v, o);
    return v;
}

__device__ __forceinline__ float4 warpsum4(float4 v) {
#pragma unroll
    for (int o = 16; o; o >>= 1) {
        v.x += __shfl_down_sync(0xffffffffu, v.x, o);
        v.y += __shfl_down_sync(0xffffffffu, v.y, o);
        v.z += __shfl_down_sync(0xffffffffu, v.z, o);
        v.w += __shfl_down_sync(0xffffffffu, v.w, o);
    }
    return v;
}

__device__ __forceinline__ float siluf(float s) { return s / (1.f + expf(-s)); }

// ============================================================
// K0: zero g_up (for split-K atomics)
// ============================================================
__global__ void zero_up_kernel() {
    int t = blockIdx.x * 256 + threadIdx.x;   // grid 1024 -> 262144 exactly
    g_up[t] = 0.f;
}

// ============================================================
// K1: split-K GEMM: g_up(64 x 4096) += inputs(64 x 1024) * W_up.
// grid (64, 4), block 256 (16x16, 4x4 micro-tile).  [R2 known-good]
// ============================================================
__global__ void __launch_bounds__(256) gemm64_kernel(
        const float* __restrict__ A, const float* __restrict__ Bm,
        int K, int N, int KC) {
    const int n0 = blockIdx.x * 64;
    const int k0 = blockIdx.y * KC;
    const int tid = threadIdx.x;
    const int tx = tid & 15, ty = tid >> 4;

    __shared__ float As[16][65];
    __shared__ float Bs[16][64];

    float acc[4][4] = {};

    for (int kt = 0; kt < KC; kt += 16) {
        __syncthreads();
#pragma unroll
        for (int i = 0; i < 4; i++) {
            int lin = tid + i * 256;
            int mm = lin >> 4, kk = lin & 15;
            As[kk][mm] = A[mm * K + k0 + kt + kk];
            int kk2 = lin >> 6, jj = lin & 63;
            Bs[kk2][jj] = Bm[(size_t)(k0 + kt + kk2) * N + n0 + jj];
        }
        __syncthreads();
#pragma unroll
        for (int kk = 0; kk < 16; kk++) {
            float4 b4 = *(const float4*)&Bs[kk][tx * 4];
            float a0 = As[kk][ty * 4 + 0];
            float a1 = As[kk][ty * 4 + 1];
            float a2 = As[kk][ty * 4 + 2];
            float a3 = As[kk][ty * 4 + 3];
            acc[0][0] += a0 * b4.x; acc[0][1] += a0 * b4.y; acc[0][2] += a0 * b4.z; acc[0][3] += a0 * b4.w;
            acc[1][0] += a1 * b4.x; acc[1][1] += a1 * b4.y; acc[1][2] += a1 * b4.z; acc[1][3] += a1 * b4.w;
            acc[2][0] += a2 * b4.x; acc[2][1] += a2 * b4.y; acc[2][2] += a2 * b4.z; acc[2][3] += a2 * b4.w;
            acc[3][0] += a3 * b4.x; acc[3][1] += a3 * b4.y; acc[3][2] += a3 * b4.z; acc[3][3] += a3 * b4.w;
        }
    }
#pragma unroll
    for (int i = 0; i < 4; i++) {
        float* crow = g_up + (size_t)(ty * 4 + i) * N + n0 + tx * 4;
        atomicAdd(crow + 0, acc[i][0]);
        atomicAdd(crow + 1, acc[i][1]);
        atomicAdd(crow + 2, acc[i][2]);
        atomicAdd(crow + 3, acc[i][3]);
    }
}

// ============================================================
// K2: FUSED conv + silu + block-diag qkv + gates + n_new/den.
// grid 64 (one per batch), block 512 (one thread per 4-ch block).
// ============================================================
__global__ void __launch_bounds__(512) fused_mid_kernel(
        const float* __restrict__ cs_in,
        const float* __restrict__ conv_w, const float* __restrict__ conv_b,
        const float* __restrict__ Wq, const float* __restrict__ Wk,
        const float* __restrict__ Wv,
        const float* __restrict__ nst, const float* __restrict__ mst,
        const float* __restrict__ Wi, const float* __restrict__ bi,
        const float* __restrict__ Wf, const float* __restrict__ bf,
        float* __restrict__ out) {
    const int b = blockIdx.x;
    const int nb = threadIdx.x;         // 0..511
    const int ch0 = nb * 4;
    const int lane = nb & 31, wid = nb >> 5;   // 16 warps

    // ---- conv + conv_state_new ----
    const float* csb = cs_in + (size_t)b * KS_ * HID_;
    float4 c0 = *(const float4*)&csb[1 * HID_ + ch0];
    float4 c1 = *(const float4*)&csb[2 * HID_ + ch0];
    float4 c2 = *(const float4*)&csb[3 * HID_ + ch0];
    float4 xv = *(const float4*)&g_up[b * 4096 + ch0];

    float* ocs = out + OUT_CS + (size_t)b * KS_ * HID_;
    *(float4*)&ocs[0 * HID_ + ch0] = c0;
    *(float4*)&ocs[1 * HID_ + ch0] = c1;
    *(float4*)&ocs[2 * HID_ + ch0] = c2;
    *(float4*)&ocs[3 * HID_ + ch0] = xv;

    float4 w0 = *(const float4*)&conv_w[0 * HID_ + ch0];
    float4 w1 = *(const float4*)&conv_w[1 * HID_ + ch0];
    float4 w2 = *(const float4*)&conv_w[2 * HID_ + ch0];
    float4 w3 = *(const float4*)&conv_w[3 * HID_ + ch0];
    float4 cb = *(const float4*)&conv_b[ch0];

    float4 s;
    s.x = c0.x * w0.x + c1.x * w1.x + c2.x * w2.x + xv.x * w3.x + cb.x;
    s.y = c0.y * w0.y + c1.y * w1.y + c2.y * w2.y + xv.y * w3.y + cb.y;
    s.z = c0.z * w0.z + c1.z * w1.z + c2.z * w2.z + xv.z * w3.z + cb.z;
    s.w = c0.w * w0.w + c1.w * w1.w + c2.w * w2.w + xv.w * w3.w + cb.w;
    float4 act = make_float4(siluf(s.x), siluf(s.y), siluf(s.z), siluf(s.w));
    *(float4*)&g_convact[b * 2048 + ch0] = act;

    // ---- block-diagonal qkv (4x4 per block) ----
    const float4* wqv = (const float4*)(Wq + nb * 16);
    const float4* wkv = (const float4*)(Wk + nb * 16);
    const float4* wvv = (const float4*)(Wv + nb * 16);
    float4 q4 = make_float4(0, 0, 0, 0), k4 = q4, v4 = q4;
    {
        float ad[4] = {act.x, act.y, act.z, act.w};
        float xd[4] = {xv.x, xv.y, xv.z, xv.w};
#pragma unroll
        for (int d = 0; d < 4; d++) {
            float4 wq = wqv[d], wk = wkv[d], wv = wvv[d];
            q4.x += ad[d] * wq.x; q4.y += ad[d] * wq.y; q4.z += ad[d] * wq.z; q4.w += ad[d] * wq.w;
            k4.x += ad[d] * wk.x; k4.y += ad[d] * wk.y; k4.z += ad[d] * wk.z; k4.w += ad[d] * wk.w;
            v4.x += xd[d] * wv.x; v4.y += xd[d] * wv.y; v4.z += xd[d] * wv.z; v4.w += xd[d] * wv.w;
        }
    }
    *(float4*)&g_q[b * 2048 + ch0] = q4;
    *(float4*)&g_k[b * 2048 + ch0] = k4;
    *(float4*)&g_v[b * 2048 + ch0] = v4;

    // ---- gate pre-activations ai[h], af[h] ----
    float4 ai = make_float4(0, 0, 0, 0), af = ai;
    {
        const float4* WiV = (const float4*)Wi;
        const float4* WfV = (const float4*)Wf;
        float qa[4] = {q4.x, q4.y, q4.z, q4.w};
        float ka[4] = {k4.x, k4.y, k4.z, k4.w};
        float va[4] = {v4.x, v4.y, v4.z, v4.w};
#pragma unroll
        for (int e = 0; e < 4; e++) {
            float4 wi = WiV[ch0 + e], wf = WfV[ch0 + e];
            ai.x += qa[e] * wi.x; ai.y += qa[e] * wi.y; ai.z += qa[e] * wi.z; ai.w += qa[e] * wi.w;
            af.x += qa[e] * wf.x; af.y += qa[e] * wf.y; af.z += qa[e] * wf.z; af.w += qa[e] * wf.w;
        }
#pragma unroll
        for (int e = 0; e < 4; e++) {
            float4 wi = WiV[2048 + ch0 + e], wf = WfV[2048 + ch0 + e];
            ai.x += ka[e] * wi.x; ai.y += ka[e] * wi.y; ai.z += ka[e] * wi.z; ai.w += ka[e] * wi.w;
            af.x += ka[e] * wf.x; af.y += ka[e] * wf.y; af.z += ka[e] * wf.z; af.w += ka[e] * wf.w;
        }
#pragma unroll
        for (int e = 0; e < 4; e++) {
            float4 wi = WiV[4096 + ch0 + e], wf = WfV[4096 + ch0 + e];
            ai.x += va[e] * wi.x; ai.y += va[e] * wi.y; ai.z += va[e] * wi.z; ai.w += va[e] * wi.w;
            af.x += va[e] * wf.x; af.y += va[e] * wf.y; af.z += va[e] * wf.z; af.w += va[e] * wf.w;
        }
    }

    __shared__ float4 sai[16], saf[16];
    __shared__ float sfp[4], sip[4], smn[4];
    __shared__ float dred[16];

    ai = warpsum4(ai); af = warpsum4(af);
    if (lane == 0) { sai[wid] = ai; saf[wid] = af; }
    __syncthreads();

    if (nb < 4) {
        int h = nb;
        float ti = 0.f, tf = 0.f;
#pragma unroll
        for (int w = 0; w < 16; w++) {
            float4 a = sai[w], f = saf[w];
            ti += (h == 0) ? a.x : (h == 1) ? a.y : (h == 2) ? a.z : a.w;
            tf += (h == 0) ? f.x : (h == 1) ? f.y : (h == 2) ? f.z : f.w;
        }
        float it = ti + bi[h];
        float ft = tf + bf[h];
        float logf_ = -(fmaxf(-ft, 0.f) + log1pf(expf(-fabsf(ft))));
        float mold = mst[b * 4 + h];
        float mnew = fmaxf(logf_ + mold, it);
        float ip = expf(it - mnew);
        float fp = expf(logf_ + mold - mnew);
        out[OUT_M + b * 4 + h] = mnew;
        g_fp[b * 4 + h] = fp; g_ip[b * 4 + h] = ip;
        sfp[h] = fp; sip[h] = ip; smn[h] = mnew;
    }
    __syncthreads();

    // ---- n_new, den partial; zero g_nom slice ----
    const int h = nb >> 7;                    // 128 threads per head
    float fp = sfp[h], ip = sip[h];
    float4 nold = *(const float4*)&nst[b * 2048 + ch0];
    float4 nn;
    nn.x = fp * nold.x + ip * KSC * k4.x;
    nn.y = fp * nold.y + ip * KSC * k4.y;
    nn.z = fp * nold.z + ip * KSC * k4.z;
    nn.w = fp * nold.w + ip * KSC * k4.w;
    *(float4*)&(out + OUT_N)[b * 2048 + ch0] = nn;
    *(float4*)&g_nom[b * 2048 + ch0] = make_float4(0, 0, 0, 0);

    float dacc = q4.x * nn.x + q4.y * nn.y + q4.z * nn.z + q4.w * nn.w;
    dacc = warpsum(dacc);
    if (lane == 0) dred[wid] = dacc;
    __syncthreads();
    if (nb < 4) {
        float ssum = dred[nb * 4] + dred[nb * 4 + 1] + dred[nb * 4 + 2] + dred[nb * 4 + 3];
        float den = fmaxf(fabsf(ssum), expf(-smn[nb])) + EPS_;
        g_den[b * 4 + nb] = den;
    }
}

// ============================================================
// K3: C_new = fp*C + ip*kh (x) vh fused with nom = q^T C_new.
// grid (4, 256), block 256.  [R2 known-good: plain ld/st]
// ============================================================
__global__ void __launch_bounds__(256) cupdate_kernel(
        const float* __restrict__ Cin, float* __restrict__ out) {
    int bh = blockIdx.y;
    int b = bh >> 2, h = bh & 3;
    int tid = threadIdx.x;
    int ty = tid >> 7;
    int tx = tid & 127;
    int e0 = tx * 4;
    int d0 = blockIdx.x * 128 + ty * 64;

    float fp = g_fp[bh], ip = g_ip[bh];

    __shared__ float sa[2][64], sq[2][64];
    if (tx < 64) {
        int gd = b * 2048 + h * 512 + d0 + tx;
        sa[ty][tx] = ip * KSC * g_k[gd];
        sq[ty][tx] = g_q[gd];
    }
    __syncthreads();

    float4 vh = *(const float4*)&g_v[b * 2048 + h * 512 + e0];

    const float* cbase = Cin + ((size_t)bh * 512 + d0) * 512 + e0;
    float* obase = out + OUT_C + ((size_t)bh * 512 + d0) * 512 + e0;

    float4 nom = make_float4(0.f, 0.f, 0.f, 0.f);
#pragma unroll 8
    for (int dd = 0; dd < 64; dd++) {
        float a  = sa[ty][dd];
        float qd = sq[ty][dd];
        float4 c = *(const float4*)(cbase + (size_t)dd * 512);
        float4 cn;
        cn.x = fp * c.x + a * vh.x;
        cn.y = fp * c.y + a * vh.y;
        cn.z = fp * c.z + a * vh.z;
        cn.w = fp * c.w + a * vh.w;
        *(float4*)(obase + (size_t)dd * 512) = cn;
        nom.x += qd * cn.x;
        nom.y += qd * cn.y;
        nom.z += qd * cn.z;
        nom.w += qd * cn.w;
    }
    float* np = &g_nom[bh * 512 + e0];
    atomicAdd(np + 0, nom.x);
    atomicAdd(np + 1, nom.y);
    atomicAdd(np + 2, nom.z);
    atomicAdd(np + 3, nom.w);
}

// ============================================================
// K4: h_tilde = nom/den, layernorm, skip, silu(z) gate; zero y.
// grid 256 x 256
// ============================================================
__global__ void __launch_bounds__(256) finalize_kernel(
        const float* __restrict__ norm_scale, const float* __restrict__ skip,
        float* __restrict__ out) {
    int bh = blockIdx.x;
    int b = bh >> 2, h = bh & 3;
    int tid = threadIdx.x;
    int lane = tid & 31, wid = tid >> 5;

    out[OUT_Y + bh * 256 + tid] = 0.f;

    float den = g_den[bh];
    float v0 = g_nom[bh * 512 + tid] / den;
    float v1 = g_nom[bh * 512 + tid + 256] / den;

    float s = v0 + v1;
    float ss = v0 * v0 + v1 * v1;
    s = warpsum(s); ss = warpsum(ss);
    __shared__ float r1[8], r2[8], st[2];
    if (lane == 0) { r1[wid] = s; r2[wid] = ss; }
    __syncthreads();
    if (tid == 0) {
        float ts = 0.f, tss = 0.f;
#pragma unroll
        for (int w = 0; w < 8; w++) { ts += r1[w]; tss += r2[w]; }
        float mu = ts / 512.f;
        float var = tss / 512.f - mu * mu;
        st[0] = mu;
        st[1] = rsqrtf(var + EPS_);
    }
    __syncthreads();
    float mu = st[0], rstd = st[1];

#pragma unroll
    for (int i = 0; i < 2; i++) {
        int e = tid + i * 256;
        int hid = h * 512 + e;
        float v = (i == 0) ? v0 : v1;
        float hn = (v - mu) * rstd * norm_scale[h * 512 + e];
        float hv = hn + skip[hid] * g_convact[b * 2048 + hid];
        float z = g_up[b * 4096 + 2048 + hid];
        g_h[b * 2048 + hid] = hv * siluf(z);
    }
}

// ============================================================
// K5: y = g_h @ W_down (64x2048x1024), split-K=8, atomics.
// ============================================================
__global__ void __launch_bounds__(256) gemm_down_kernel(
        const float* __restrict__ Wd, float* __restrict__ out, int KC) {
    const float* A = g_h;
    const int K = HID_, N = F_;
    const int n0 = blockIdx.x * 64;
    const int k0 = blockIdx.y * KC;
    const int tid = threadIdx.x;
    const int tx = tid & 15, ty = tid >> 4;
    __shared__ float As[16][65];
    __shared__ float Bs[16][64];
    float acc[4][4] = {};
    for (int kt = 0; kt < KC; kt += 16) {
        __syncthreads();
#pragma unroll
        for (int i = 0; i < 4; i++) {
            int lin = tid + i * 256;
            int mm = lin >> 4, kk = lin & 15;
            As[kk][mm] = A[mm * K + k0 + kt + kk];
            int kk2 = lin >> 6, jj = lin & 63;
            Bs[kk2][jj] = Wd[(size_t)(k0 + kt + kk2) * N + n0 + jj];
        }
        __syncthreads();
#pragma unroll
        for (int kk = 0; kk < 16; kk++) {
            float4 b4 = *(const float4*)&Bs[kk][tx * 4];
            float a0 = As[kk][ty * 4 + 0];
            float a1 = As[kk][ty * 4 + 1];
            float a2 = As[kk][ty * 4 + 2];
            float a3 = As[kk][ty * 4 + 3];
            acc[0][0] += a0 * b4.x; acc[0][1] += a0 * b4.y; acc[0][2] += a0 * b4.z; acc[0][3] += a0 * b4.w;
            acc[1][0] += a1 * b4.x; acc[1][1] += a1 * b4.y; acc[1][2] += a1 * b4.z; acc[1][3] += a1 * b4.w;
            acc[2][0] += a2 * b4.x; acc[2][1] += a2 * b4.y; acc[2][2] += a2 * b4.z; acc[2][3] += a2 * b4.w;
            acc[3][0] += a3 * b4.x; acc[3][1] += a3 * b4.y; acc[3][2] += a3 * b4.z; acc[3][3] += a3 * b4.w;
        }
    }
#pragma unroll
    for (int i = 0; i < 4; i++) {
        float* crow = out + OUT_Y + (size_t)(ty * 4 + i) * N + n0 + tx * 4;
        atomicAdd(crow + 0, acc[i][0]);
        atomicAdd(crow + 1, acc[i][1]);
        atomicAdd(crow + 2, acc[i][2]);
        atomicAdd(crow + 3, acc[i][3]);
    }
}

extern "C" void kernel_launch(void* const* d_in, const int* in_sizes, int n_in,
                              void* d_out, int out_size) {
    const float* inputs     = (const float*)d_in[0];
    const float* C          = (const float*)d_in[1];
    const float* n_state    = (const float*)d_in[2];
    const float* m_state    = (const float*)d_in[3];
    const float* conv_state = (const float*)d_in[4];
    const float* W_up       = (const float*)d_in[5];
    const float* conv_w     = (const float*)d_in[6];
    const float* conv_b     = (const float*)d_in[7];
    const float* Wq         = (const float*)d_in[8];
    const float* Wk         = (const float*)d_in[9];
    const float* Wv         = (const float*)d_in[10];
    const float* Wi         = (const float*)d_in[11];
    const float* bi         = (const float*)d_in[12];
    const float* Wf         = (const float*)d_in[13];
    const float* bf         = (const float*)d_in[14];
    const float* norm_scale = (const float*)d_in[15];
    const float* skip       = (const float*)d_in[16];
    const float* W_down     = (const float*)d_in[17];
    float* out = (float*)d_out;

    // K0: zero g_up for split-K atomics
    zero_up_kernel<<<1024, 256>>>();

    // K1: up = inputs @ W_up (64x1024x4096), split-K=4  [R2 known-good]
    gemm64_kernel<<<dim3(64, 4), 256>>>(inputs, W_up, F_, 2 * HID_, 256);

    // K2: fused conv/qkv/gates/n_new/den
    fused_mid_kernel<<<64, 512>>>(conv_state, conv_w, conv_b, Wq, Wk, Wv,
                                  n_state, m_state, Wi, bi, Wf, bf, out);

    // K3: C update fused with q^T C_new
    cupdate_kernel<<<dim3(4, 256), 256>>>(C, out);

    // K4: layernorm epilogue; zero y
    finalize_kernel<<<256, 256>>>(norm_scale, skip, out);

    // K5: down projection, split-K=8
    gemm_down_kernel<<<dim3(16, 8), 256>>>(W_down, out, 256);
}

// round 6
// speedup vs baseline: 1.3486x; 1.0383x over previous
#include <cuda_runtime.h>
#include <math.h>

#define B_    64
#define F_    1024
#define HID_  2048
#define NH_   4
#define KS_   4
#define HD_   512
#define EPS_  1e-6f
#define KSC   0.044194173824159216f   // 1/sqrt(512)

// ---- output layout (float count offsets) ----
#define OUT_Y   0
#define OUT_C   (B_*F_)                              // 65536
#define OUT_N   (OUT_C + B_*NH_*HD_*HD_)             // 67174400
#define OUT_M   (OUT_N + B_*NH_*HD_)                 // 67305472
#define OUT_CS  (OUT_M + B_*NH_)                     // 67305728

// ---- scratch ----
__device__ __align__(16) float g_upp[4][B_ * 2 * HID_];   // split-K partials (x|z)
__device__ __align__(16) float g_convact[B_ * HID_];
__device__ __align__(16) float g_q[B_ * HID_];
__device__ __align__(16) float g_k[B_ * HID_];            // UNSCALED k
__device__ __align__(16) float g_v[B_ * HID_];
__device__ float g_fp[B_ * NH_];
__device__ float g_ip[B_ * NH_];
__device__ float g_den[B_ * NH_];
__device__ __align__(16) float g_nom[B_ * NH_ * HD_];
__device__ __align__(16) float g_h[B_ * HID_];

__device__ __forceinline__ float warpsum(float v) {
#pragma unroll
    for (int o = 16; o; o >>= 1) v += __shfl_down_sync(0xffffffffu, v, o);
    return v;
}

__device__ __forceinline__ float4 warpsum4(float4 v) {
#pragma unroll
    for (int o = 16; o; o >>= 1) {
        v.x += __shfl_down_sync(0xffffffffu, v.x, o);
        v.y += __shfl_down_sync(0xffffffffu, v.y, o);
        v.z += __shfl_down_sync(0xffffffffu, v.z, o);
        v.w += __shfl_down_sync(0xffffffffu, v.w, o);
    }
    return v;
}

__device__ __forceinline__ float siluf(float s) { return s / (1.f + expf(-s)); }

// ============================================================
// K1: split-K GEMM, partial-buffer outputs (no atomics, no zero).
// g_upp[ky](64 x 4096) = inputs(64 x 1024[slice ky]) * W_up[slice].
// grid (64, 4), block 256 (16x16, 4x4 micro-tile).
// ============================================================
__global__ void __launch_bounds__(256) gemm_up_kernel(
        const float* __restrict__ A, const float* __restrict__ Bm) {
    const int K = F_, N = 2 * HID_, KC = 256;
    const int n0 = blockIdx.x * 64;
    const int ky = blockIdx.y;
    const int k0 = ky * KC;
    const int tid = threadIdx.x;
    const int tx = tid & 15, ty = tid >> 4;

    __shared__ float As[16][65];
    __shared__ float Bs[16][64];

    float acc[4][4] = {};

    for (int kt = 0; kt < KC; kt += 16) {
        __syncthreads();
#pragma unroll
        for (int i = 0; i < 4; i++) {
            int lin = tid + i * 256;
            int mm = lin >> 4, kk = lin & 15;
            As[kk][mm] = A[mm * K + k0 + kt + kk];
            int kk2 = lin >> 6, jj = lin & 63;
            Bs[kk2][jj] = Bm[(size_t)(k0 + kt + kk2) * N + n0 + jj];
        }
        __syncthreads();
#pragma unroll
        for (int kk = 0; kk < 16; kk++) {
            float4 b4 = *(const float4*)&Bs[kk][tx * 4];
            float a0 = As[kk][ty * 4 + 0];
            float a1 = As[kk][ty * 4 + 1];
            float a2 = As[kk][ty * 4 + 2];
            float a3 = As[kk][ty * 4 + 3];
            acc[0][0] += a0 * b4.x; acc[0][1] += a0 * b4.y; acc[0][2] += a0 * b4.z; acc[0][3] += a0 * b4.w;
            acc[1][0] += a1 * b4.x; acc[1][1] += a1 * b4.y; acc[1][2] += a1 * b4.z; acc[1][3] += a1 * b4.w;
            acc[2][0] += a2 * b4.x; acc[2][1] += a2 * b4.y; acc[2][2] += a2 * b4.z; acc[2][3] += a2 * b4.w;
            acc[3][0] += a3 * b4.x; acc[3][1] += a3 * b4.y; acc[3][2] += a3 * b4.z; acc[3][3] += a3 * b4.w;
        }
    }
#pragma unroll
    for (int i = 0; i < 4; i++) {
        float4 r = make_float4(acc[i][0], acc[i][1], acc[i][2], acc[i][3]);
        *(float4*)&g_upp[ky][(size_t)(ty * 4 + i) * N + n0 + tx * 4] = r;
    }
}

// ============================================================
// K2: FUSED conv + silu + block-diag qkv + gates + n_new/den.
// grid 64 (one per batch), block 512 (one thread per 4-ch block).
// ============================================================
__global__ void __launch_bounds__(512) fused_mid_kernel(
        const float* __restrict__ cs_in,
        const float* __restrict__ conv_w, const float* __restrict__ conv_b,
        const float* __restrict__ Wq, const float* __restrict__ Wk,
        const float* __restrict__ Wv,
        const float* __restrict__ nst, const float* __restrict__ mst,
        const float* __restrict__ Wi, const float* __restrict__ bi,
        const float* __restrict__ Wf, const float* __restrict__ bf,
        float* __restrict__ out) {
    const int b = blockIdx.x;
    const int nb = threadIdx.x;         // 0..511
    const int ch0 = nb * 4;
    const int lane = nb & 31, wid = nb >> 5;   // 16 warps

    // ---- x = sum of split-K partials ----
    float4 xv;
    {
        float4 p0 = *(const float4*)&g_upp[0][b * 4096 + ch0];
        float4 p1 = *(const float4*)&g_upp[1][b * 4096 + ch0];
        float4 p2 = *(const float4*)&g_upp[2][b * 4096 + ch0];
        float4 p3 = *(const float4*)&g_upp[3][b * 4096 + ch0];
        xv.x = (p0.x + p1.x) + (p2.x + p3.x);
        xv.y = (p0.y + p1.y) + (p2.y + p3.y);
        xv.z = (p0.z + p1.z) + (p2.z + p3.z);
        xv.w = (p0.w + p1.w) + (p2.w + p3.w);
    }

    // ---- conv + conv_state_new ----
    const float* csb = cs_in + (size_t)b * KS_ * HID_;
    float4 c0 = *(const float4*)&csb[1 * HID_ + ch0];
    float4 c1 = *(const float4*)&csb[2 * HID_ + ch0];
    float4 c2 = *(const float4*)&csb[3 * HID_ + ch0];

    float* ocs = out + OUT_CS + (size_t)b * KS_ * HID_;
    *(float4*)&ocs[0 * HID_ + ch0] = c0;
    *(float4*)&ocs[1 * HID_ + ch0] = c1;
    *(float4*)&ocs[2 * HID_ + ch0] = c2;
    *(float4*)&ocs[3 * HID_ + ch0] = xv;

    float4 w0 = *(const float4*)&conv_w[0 * HID_ + ch0];
    float4 w1 = *(const float4*)&conv_w[1 * HID_ + ch0];
    float4 w2 = *(const float4*)&conv_w[2 * HID_ + ch0];
    float4 w3 = *(const float4*)&conv_w[3 * HID_ + ch0];
    float4 cb = *(const float4*)&conv_b[ch0];

    float4 s;
    s.x = c0.x * w0.x + c1.x * w1.x + c2.x * w2.x + xv.x * w3.x + cb.x;
    s.y = c0.y * w0.y + c1.y * w1.y + c2.y * w2.y + xv.y * w3.y + cb.y;
    s.z = c0.z * w0.z + c1.z * w1.z + c2.z * w2.z + xv.z * w3.z + cb.z;
    s.w = c0.w * w0.w + c1.w * w1.w + c2.w * w2.w + xv.w * w3.w + cb.w;
    float4 act = make_float4(siluf(s.x), siluf(s.y), siluf(s.z), siluf(s.w));
    *(float4*)&g_convact[b * 2048 + ch0] = act;

    // ---- block-diagonal qkv (4x4 per block) ----
    const float4* wqv = (const float4*)(Wq + nb * 16);
    const float4* wkv = (const float4*)(Wk + nb * 16);
    const float4* wvv = (const float4*)(Wv + nb * 16);
    float4 q4 = make_float4(0, 0, 0, 0), k4 = q4, v4 = q4;
    {
        float ad[4] = {act.x, act.y, act.z, act.w};
        float xd[4] = {xv.x, xv.y, xv.z, xv.w};
#pragma unroll
        for (int d = 0; d < 4; d++) {
            float4 wq = wqv[d], wk = wkv[d], wv = wvv[d];
            q4.x += ad[d] * wq.x; q4.y += ad[d] * wq.y; q4.z += ad[d] * wq.z; q4.w += ad[d] * wq.w;
            k4.x += ad[d] * wk.x; k4.y += ad[d] * wk.y; k4.z += ad[d] * wk.z; k4.w += ad[d] * wk.w;
            v4.x += xd[d] * wv.x; v4.y += xd[d] * wv.y; v4.z += xd[d] * wv.z; v4.w += xd[d] * wv.w;
        }
    }
    *(float4*)&g_q[b * 2048 + ch0] = q4;
    *(float4*)&g_k[b * 2048 + ch0] = k4;
    *(float4*)&g_v[b * 2048 + ch0] = v4;

    // ---- gate pre-activations ai[h], af[h] ----
    float4 ai = make_float4(0, 0, 0, 0), af = ai;
    {
        const float4* WiV = (const float4*)Wi;
        const float4* WfV = (const float4*)Wf;
        float qa[4] = {q4.x, q4.y, q4.z, q4.w};
        float ka[4] = {k4.x, k4.y, k4.z, k4.w};
        float va[4] = {v4.x, v4.y, v4.z, v4.w};
#pragma unroll
        for (int e = 0; e < 4; e++) {
            float4 wi = WiV[ch0 + e], wf = WfV[ch0 + e];
            ai.x += qa[e] * wi.x; ai.y += qa[e] * wi.y; ai.z += qa[e] * wi.z; ai.w += qa[e] * wi.w;
            af.x += qa[e] * wf.x; af.y += qa[e] * wf.y; af.z += qa[e] * wf.z; af.w += qa[e] * wf.w;
        }
#pragma unroll
        for (int e = 0; e < 4; e++) {
            float4 wi = WiV[2048 + ch0 + e], wf = WfV[2048 + ch0 + e];
            ai.x += ka[e] * wi.x; ai.y += ka[e] * wi.y; ai.z += ka[e] * wi.z; ai.w += ka[e] * wi.w;
            af.x += ka[e] * wf.x; af.y += ka[e] * wf.y; af.z += ka[e] * wf.z; af.w += ka[e] * wf.w;
        }
#pragma unroll
        for (int e = 0; e < 4; e++) {
            float4 wi = WiV[4096 + ch0 + e], wf = WfV[4096 + ch0 + e];
            ai.x += va[e] * wi.x; ai.y += va[e] * wi.y; ai.z += va[e] * wi.z; ai.w += va[e] * wi.w;
            af.x += va[e] * wf.x; af.y += va[e] * wf.y; af.z += va[e] * wf.z; af.w += va[e] * wf.w;
        }
    }

    __shared__ float4 sai[16], saf[16];
    __shared__ float sfp[4], sip[4], smn[4];
    __shared__ float dred[16];

    ai = warpsum4(ai); af = warpsum4(af);
    if (lane == 0) { sai[wid] = ai; saf[wid] = af; }
    __syncthreads();

    if (nb < 4) {
        int h = nb;
        float ti = 0.f, tf = 0.f;
#pragma unroll
        for (int w = 0; w < 16; w++) {
            float4 a = sai[w], f = saf[w];
            ti += (h == 0) ? a.x : (h == 1) ? a.y : (h == 2) ? a.z : a.w;
            tf += (h == 0) ? f.x : (h == 1) ? f.y : (h == 2) ? f.z : f.w;
        }
        float it = ti + bi[h];
        float ft = tf + bf[h];
        float logf_ = -(fmaxf(-ft, 0.f) + log1pf(expf(-fabsf(ft))));
        float mold = mst[b * 4 + h];
        float mnew = fmaxf(logf_ + mold, it);
        float ip = expf(it - mnew);
        float fp = expf(logf_ + mold - mnew);
        out[OUT_M + b * 4 + h] = mnew;
        g_fp[b * 4 + h] = fp; g_ip[b * 4 + h] = ip;
        sfp[h] = fp; sip[h] = ip; smn[h] = mnew;
    }
    __syncthreads();

    // ---- n_new, den partial; zero g_nom slice ----
    const int h = nb >> 7;                    // 128 threads per head
    float fp = sfp[h], ip = sip[h];
    float4 nold = *(const float4*)&nst[b * 2048 + ch0];
    float4 nn;
    nn.x = fp * nold.x + ip * KSC * k4.x;
    nn.y = fp * nold.y + ip * KSC * k4.y;
    nn.z = fp * nold.z + ip * KSC * k4.z;
    nn.w = fp * nold.w + ip * KSC * k4.w;
    *(float4*)&(out + OUT_N)[b * 2048 + ch0] = nn;
    *(float4*)&g_nom[b * 2048 + ch0] = make_float4(0, 0, 0, 0);

    float dacc = q4.x * nn.x + q4.y * nn.y + q4.z * nn.z + q4.w * nn.w;
    dacc = warpsum(dacc);
    if (lane == 0) dred[wid] = dacc;
    __syncthreads();
    if (nb < 4) {
        float ssum = dred[nb * 4] + dred[nb * 4 + 1] + dred[nb * 4 + 2] + dred[nb * 4 + 3];
        float den = fmaxf(fabsf(ssum), expf(-smn[nb])) + EPS_;
        g_den[b * 4 + nb] = den;
    }
}

// ============================================================
// K3: C_new = fp*C + ip*kh (x) vh fused with nom = q^T C_new.
// grid (16, 256) = 4096 blocks (32 d-rows each), block 256.
// Multi-wave structure for better tail behavior.
// ============================================================
__global__ void __launch_bounds__(256) cupdate_kernel(
        const float* __restrict__ Cin, float* __restrict__ out) {
    int bh = blockIdx.y;
    int b = bh >> 2, h = bh & 3;
    int tid = threadIdx.x;
    int ty = tid >> 7;
    int tx = tid & 127;
    int e0 = tx * 4;
    int d0 = blockIdx.x * 32 + ty * 16;

    float fp = g_fp[bh], ip = g_ip[bh];

    __shared__ float sa[2][16], sq[2][16];
    if (tx < 16) {
        int gd = b * 2048 + h * 512 + d0 + tx;
        sa[ty][tx] = ip * KSC * g_k[gd];
        sq[ty][tx] = g_q[gd];
    }
    __syncthreads();

    float4 vh = *(const float4*)&g_v[b * 2048 + h * 512 + e0];

    const float* cbase = Cin + ((size_t)bh * 512 + d0) * 512 + e0;
    float* obase = out + OUT_C + ((size_t)bh * 512 + d0) * 512 + e0;

    float4 nom = make_float4(0.f, 0.f, 0.f, 0.f);
#pragma unroll
    for (int dd = 0; dd < 16; dd++) {
        float a  = sa[ty][dd];
        float qd = sq[ty][dd];
        float4 c = *(const float4*)(cbase + (size_t)dd * 512);
        float4 cn;
        cn.x = fp * c.x + a * vh.x;
        cn.y = fp * c.y + a * vh.y;
        cn.z = fp * c.z + a * vh.z;
        cn.w = fp * c.w + a * vh.w;
        *(float4*)(obase + (size_t)dd * 512) = cn;
        nom.x += qd * cn.x;
        nom.y += qd * cn.y;
        nom.z += qd * cn.z;
        nom.w += qd * cn.w;
    }
    // combine the two ty halves through one atomic set per (tx, half)? No:
    // both halves hit the same g_nom address; atomics handle it.
    float* np = &g_nom[bh * 512 + e0];
    atomicAdd(np + 0, nom.x);
    atomicAdd(np + 1, nom.y);
    atomicAdd(np + 2, nom.z);
    atomicAdd(np + 3, nom.w);
}

// ============================================================
// K4: h_tilde = nom/den, layernorm, skip, silu(z) gate; zero y.
// grid 256 x 256
// ============================================================
__global__ void __launch_bounds__(256) finalize_kernel(
        const float* __restrict__ norm_scale, const float* __restrict__ skip,
        float* __restrict__ out) {
    int bh = blockIdx.x;
    int b = bh >> 2, h = bh & 3;
    int tid = threadIdx.x;
    int lane = tid & 31, wid = tid >> 5;

    out[OUT_Y + bh * 256 + tid] = 0.f;

    float den = g_den[bh];
    float v0 = g_nom[bh * 512 + tid] / den;
    float v1 = g_nom[bh * 512 + tid + 256] / den;

    float s = v0 + v1;
    float ss = v0 * v0 + v1 * v1;
    s = warpsum(s); ss = warpsum(ss);
    __shared__ float r1[8], r2[8], st[2];
    if (lane == 0) { r1[wid] = s; r2[wid] = ss; }
    __syncthreads();
    if (tid == 0) {
        float ts = 0.f, tss = 0.f;
#pragma unroll
        for (int w = 0; w < 8; w++) { ts += r1[w]; tss += r2[w]; }
        float mu = ts / 512.f;
        float var = tss / 512.f - mu * mu;
        st[0] = mu;
        st[1] = rsqrtf(var + EPS_);
    }
    __syncthreads();
    float mu = st[0], rstd = st[1];

#pragma unroll
    for (int i = 0; i < 2; i++) {
        int e = tid + i * 256;
        int hid = h * 512 + e;
        float v = (i == 0) ? v0 : v1;
        float hn = (v - mu) * rstd * norm_scale[h * 512 + e];
        float hv = hn + skip[hid] * g_convact[b * 2048 + hid];
        int zi = b * 4096 + 2048 + hid;
        float z = (g_upp[0][zi] + g_upp[1][zi]) + (g_upp[2][zi] + g_upp[3][zi]);
        g_h[b * 2048 + hid] = hv * siluf(z);
    }
}

// ============================================================
// K5: y = g_h @ W_down (64x2048x1024), split-K=8, atomics.
// ============================================================
__global__ void __launch_bounds__(256) gemm_down_kernel(
        const float* __restrict__ Wd, float* __restrict__ out, int KC) {
    const float* A = g_h;
    const int K = HID_, N = F_;
    const int n0 = blockIdx.x * 64;
    const int k0 = blockIdx.y * KC;
    const int tid = threadIdx.x;
    const int tx = tid & 15, ty = tid >> 4;
    __shared__ float As[16][65];
    __shared__ float Bs[16][64];
    float acc[4][4] = {};
    for (int kt = 0; kt < KC; kt += 16) {
        __syncthreads();
#pragma unroll
        for (int i = 0; i < 4; i++) {
            int lin = tid + i * 256;
            int mm = lin >> 4, kk = lin & 15;
            As[kk][mm] = A[mm * K + k0 + kt + kk];
            int kk2 = lin >> 6, jj = lin & 63;
            Bs[kk2][jj] = Wd[(size_t)(k0 + kt + kk2) * N + n0 + jj];
        }
        __syncthreads();
#pragma unroll
        for (int kk = 0; kk < 16; kk++) {
            float4 b4 = *(const float4*)&Bs[kk][tx * 4];
            float a0 = As[kk][ty * 4 + 0];
            float a1 = As[kk][ty * 4 + 1];
            float a2 = As[kk][ty * 4 + 2];
            float a3 = As[kk][ty * 4 + 3];
            acc[0][0] += a0 * b4.x; acc[0][1] += a0 * b4.y; acc[0][2] += a0 * b4.z; acc[0][3] += a0 * b4.w;
            acc[1][0] += a1 * b4.x; acc[1][1] += a1 * b4.y; acc[1][2] += a1 * b4.z; acc[1][3] += a1 * b4.w;
            acc[2][0] += a2 * b4.x; acc[2][1] += a2 * b4.y; acc[2][2] += a2 * b4.z; acc[2][3] += a2 * b4.w;
            acc[3][0] += a3 * b4.x; acc[3][1] += a3 * b4.y; acc[3][2] += a3 * b4.z; acc[3][3] += a3 * b4.w;
        }
    }
#pragma unroll
    for (int i = 0; i < 4; i++) {
        float* crow = out + OUT_Y + (size_t)(ty * 4 + i) * N + n0 + tx * 4;
        atomicAdd(crow + 0, acc[i][0]);
        atomicAdd(crow + 1, acc[i][1]);
        atomicAdd(crow + 2, acc[i][2]);
        atomicAdd(crow + 3, acc[i][3]);
    }
}

extern "C" void kernel_launch(void* const* d_in, const int* in_sizes, int n_in,
                              void* d_out, int out_size) {
    const float* inputs     = (const float*)d_in[0];
    const float* C          = (const float*)d_in[1];
    const float* n_state    = (const float*)d_in[2];
    const float* m_state    = (const float*)d_in[3];
    const float* conv_state = (const float*)d_in[4];
    const float* W_up       = (const float*)d_in[5];
    const float* conv_w     = (const float*)d_in[6];
    const float* conv_b     = (const float*)d_in[7];
    const float* Wq         = (const float*)d_in[8];
    const float* Wk         = (const float*)d_in[9];
    const float* Wv         = (const float*)d_in[10];
    const float* Wi         = (const float*)d_in[11];
    const float* bi         = (const float*)d_in[12];
    const float* Wf         = (const float*)d_in[13];
    const float* bf         = (const float*)d_in[14];
    const float* norm_scale = (const float*)d_in[15];
    const float* skip       = (const float*)d_in[16];
    const float* W_down     = (const float*)d_in[17];
    float* out = (float*)d_out;

    // K1: up = inputs @ W_up (64x1024x4096), split-K=4, partial buffers
    gemm_up_kernel<<<dim3(64, 4), 256>>>(inputs, W_up);

    // K2: fused conv/qkv/gates/n_new/den
    fused_mid_kernel<<<64, 512>>>(conv_state, conv_w, conv_b, Wq, Wk, Wv,
                                  n_state, m_state, Wi, bi, Wf, bf, out);

    // K3: C update fused with q^T C_new (4096 blocks, 32 rows each)
    cupdate_kernel<<<dim3(16, 256), 256>>>(C, out);

    // K4: layernorm epilogue; zero y
    finalize_kernel<<<256, 256>>>(norm_scale, skip, out);

    // K5: down projection, split-K=8
    gemm_down_kernel<<<dim3(16, 8), 256>>>(W_down, out, 256);
}

// round 9
// speedup vs baseline: 1.4015x; 1.0392x over previous
#include <cuda_runtime.h>
#include <math.h>

#define B_    64
#define F_    1024
#define HID_  2048
#define NH_   4
#define KS_   4
#define HD_   512
#define EPS_  1e-6f
#define KSC   0.044194173824159216f   // 1/sqrt(512)
#define NUP   8                        // up-GEMM split-K factor

// ---- output layout (float count offsets) ----
#define OUT_Y   0
#define OUT_C   (B_*F_)                              // 65536
#define OUT_N   (OUT_C + B_*NH_*HD_*HD_)             // 67174400
#define OUT_M   (OUT_N + B_*NH_*HD_)                 // 67305472
#define OUT_CS  (OUT_M + B_*NH_)                     // 67305728

// ---- scratch ----
__device__ __align__(16) float g_upp[NUP][B_ * 2 * HID_];  // split-K partials (x|z)
__device__ __align__(16) float g_convact[B_ * HID_];
__device__ __align__(16) float g_q[B_ * HID_];
__device__ __align__(16) float g_k[B_ * HID_];             // UNSCALED k
__device__ __align__(16) float g_v[B_ * HID_];
__device__ float g_fp[B_ * NH_];
__device__ float g_ip[B_ * NH_];
__device__ float g_den[B_ * NH_];
__device__ __align__(16) float g_nom[B_ * NH_ * HD_];
__device__ __align__(16) float g_h[B_ * HID_];
__device__ unsigned g_cnt[B_ * NH_];                       // ticket counters

__device__ __forceinline__ float warpsum(float v) {
#pragma unroll
    for (int o = 16; o; o >>= 1) v += __shfl_down_sync(0xffffffffu, v, o);
    return v;
}

__device__ __forceinline__ float4 warpsum4(float4 v) {
#pragma unroll
    for (int o = 16; o; o >>= 1) {
        v.x += __shfl_down_sync(0xffffffffu, v.x, o);
        v.y += __shfl_down_sync(0xffffffffu, v.y, o);
        v.z += __shfl_down_sync(0xffffffffu, v.z, o);
        v.w += __shfl_down_sync(0xffffffffu, v.w, o);
    }
    return v;
}

__device__ __forceinline__ float siluf(float s) { return s / (1.f + expf(-s)); }

// ============================================================
// K1: split-K GEMM, partial-buffer outputs (no atomics).
// g_upp[ky](64 x 4096) = inputs(64 x 128[slice ky]) * W_up[slice].
// grid (64, 8), block 256 (16x16, 4x4 micro-tile).
// ============================================================
__global__ void __launch_bounds__(256) gemm_up_kernel(
        const float* __restrict__ A, const float* __restrict__ Bm) {
    const int K = F_, N = 2 * HID_, KC = F_ / NUP;   // 128
    const int n0 = blockIdx.x * 64;
    const int ky = blockIdx.y;
    const int k0 = ky * KC;
    const int tid = threadIdx.x;
    const int tx = tid & 15, ty = tid >> 4;

    __shared__ float As[16][65];
    __shared__ float Bs[16][64];

    float acc[4][4] = {};

    for (int kt = 0; kt < KC; kt += 16) {
        __syncthreads();
#pragma unroll
        for (int i = 0; i < 4; i++) {
            int lin = tid + i * 256;
            int mm = lin >> 4, kk = lin & 15;
            As[kk][mm] = A[mm * K + k0 + kt + kk];
            int kk2 = lin >> 6, jj = lin & 63;
            Bs[kk2][jj] = Bm[(size_t)(k0 + kt + kk2) * N + n0 + jj];
        }
        __syncthreads();
#pragma unroll
        for (int kk = 0; kk < 16; kk++) {
            float4 b4 = *(const float4*)&Bs[kk][tx * 4];
            float a0 = As[kk][ty * 4 + 0];
            float a1 = As[kk][ty * 4 + 1];
            float a2 = As[kk][ty * 4 + 2];
            float a3 = As[kk][ty * 4 + 3];
            acc[0][0] += a0 * b4.x; acc[0][1] += a0 * b4.y; acc[0][2] += a0 * b4.z; acc[0][3] += a0 * b4.w;
            acc[1][0] += a1 * b4.x; acc[1][1] += a1 * b4.y; acc[1][2] += a1 * b4.z; acc[1][3] += a1 * b4.w;
            acc[2][0] += a2 * b4.x; acc[2][1] += a2 * b4.y; acc[2][2] += a2 * b4.z; acc[2][3] += a2 * b4.w;
            acc[3][0] += a3 * b4.x; acc[3][1] += a3 * b4.y; acc[3][2] += a3 * b4.z; acc[3][3] += a3 * b4.w;
        }
    }
#pragma unroll
    for (int i = 0; i < 4; i++) {
        float4 r = make_float4(acc[i][0], acc[i][1], acc[i][2], acc[i][3]);
        *(float4*)&g_upp[ky][(size_t)(ty * 4 + i) * N + n0 + tx * 4] = r;
    }
}

// ============================================================
// K2: FUSED conv + silu + block-diag qkv + gates + n_new/den.
// Also: zero y region, zero ticket counters, zero g_nom.
// grid 64 (one per batch), block 512.
// ============================================================
__global__ void __launch_bounds__(512) fused_mid_kernel(
        const float* __restrict__ cs_in,
        const float* __restrict__ conv_w, const float* __restrict__ conv_b,
        const float* __restrict__ Wq, const float* __restrict__ Wk,
        const float* __restrict__ Wv,
        const float* __restrict__ nst, const float* __restrict__ mst,
        const float* __restrict__ Wi, const float* __restrict__ bi,
        const float* __restrict__ Wf, const float* __restrict__ bf,
        float* __restrict__ out) {
    const int b = blockIdx.x;
    const int nb = threadIdx.x;         // 0..511
    const int ch0 = nb * 4;
    const int lane = nb & 31, wid = nb >> 5;   // 16 warps

    // ---- housekeeping: zero y row b, ticket counters ----
    out[OUT_Y + b * 1024 + nb] = 0.f;
    out[OUT_Y + b * 1024 + nb + 512] = 0.f;
    if (nb < 4) g_cnt[b * 4 + nb] = 0u;

    // ---- x = sum of split-K partials ----
    float4 xv = make_float4(0.f, 0.f, 0.f, 0.f);
#pragma unroll
    for (int p = 0; p < NUP; p++) {
        float4 pp = *(const float4*)&g_upp[p][b * 4096 + ch0];
        xv.x += pp.x; xv.y += pp.y; xv.z += pp.z; xv.w += pp.w;
    }

    // ---- conv + conv_state_new ----
    const float* csb = cs_in + (size_t)b * KS_ * HID_;
    float4 c0 = *(const float4*)&csb[1 * HID_ + ch0];
    float4 c1 = *(const float4*)&csb[2 * HID_ + ch0];
    float4 c2 = *(const float4*)&csb[3 * HID_ + ch0];

    float* ocs = out + OUT_CS + (size_t)b * KS_ * HID_;
    *(float4*)&ocs[0 * HID_ + ch0] = c0;
    *(float4*)&ocs[1 * HID_ + ch0] = c1;
    *(float4*)&ocs[2 * HID_ + ch0] = c2;
    *(float4*)&ocs[3 * HID_ + ch0] = xv;

    float4 w0 = *(const float4*)&conv_w[0 * HID_ + ch0];
    float4 w1 = *(const float4*)&conv_w[1 * HID_ + ch0];
    float4 w2 = *(const float4*)&conv_w[2 * HID_ + ch0];
    float4 w3 = *(const float4*)&conv_w[3 * HID_ + ch0];
    float4 cb = *(const float4*)&conv_b[ch0];

    float4 s;
    s.x = c0.x * w0.x + c1.x * w1.x + c2.x * w2.x + xv.x * w3.x + cb.x;
    s.y = c0.y * w0.y + c1.y * w1.y + c2.y * w2.y + xv.y * w3.y + cb.y;
    s.z = c0.z * w0.z + c1.z * w1.z + c2.z * w2.z + xv.z * w3.z + cb.z;
    s.w = c0.w * w0.w + c1.w * w1.w + c2.w * w2.w + xv.w * w3.w + cb.w;
    float4 act = make_float4(siluf(s.x), siluf(s.y), siluf(s.z), siluf(s.w));
    *(float4*)&g_convact[b * 2048 + ch0] = act;

    // ---- block-diagonal qkv (4x4 per block) ----
    const float4* wqv = (const float4*)(Wq + nb * 16);
    const float4* wkv = (const float4*)(Wk + nb * 16);
    const float4* wvv = (const float4*)(Wv + nb * 16);
    float4 q4 = make_float4(0, 0, 0, 0), k4 = q4, v4 = q4;
    {
        float ad[4] = {act.x, act.y, act.z, act.w};
        float xd[4] = {xv.x, xv.y, xv.z, xv.w};
#pragma unroll
        for (int d = 0; d < 4; d++) {
            float4 wq = wqv[d], wk = wkv[d], wv = wvv[d];
            q4.x += ad[d] * wq.x; q4.y += ad[d] * wq.y; q4.z += ad[d] * wq.z; q4.w += ad[d] * wq.w;
            k4.x += ad[d] * wk.x; k4.y += ad[d] * wk.y; k4.z += ad[d] * wk.z; k4.w += ad[d] * wk.w;
            v4.x += xd[d] * wv.x; v4.y += xd[d] * wv.y; v4.z += xd[d] * wv.z; v4.w += xd[d] * wv.w;
        }
    }
    *(float4*)&g_q[b * 2048 + ch0] = q4;
    *(float4*)&g_k[b * 2048 + ch0] = k4;
    *(float4*)&g_v[b * 2048 + ch0] = v4;

    // ---- gate pre-activations ai[h], af[h] ----
    float4 ai = make_float4(0, 0, 0, 0), af = ai;
    {
        const float4* WiV = (const float4*)Wi;
        const float4* WfV = (const float4*)Wf;
        float qa[4] = {q4.x, q4.y, q4.z, q4.w};
        float ka[4] = {k4.x, k4.y, k4.z, k4.w};
        float va[4] = {v4.x, v4.y, v4.z, v4.w};
#pragma unroll
        for (int e = 0; e < 4; e++) {
            float4 wi = WiV[ch0 + e], wf = WfV[ch0 + e];
            ai.x += qa[e] * wi.x; ai.y += qa[e] * wi.y; ai.z += qa[e] * wi.z; ai.w += qa[e] * wi.w;
            af.x += qa[e] * wf.x; af.y += qa[e] * wf.y; af.z += qa[e] * wf.z; af.w += qa[e] * wf.w;
        }
#pragma unroll
        for (int e = 0; e < 4; e++) {
            float4 wi = WiV[2048 + ch0 + e], wf = WfV[2048 + ch0 + e];
            ai.x += ka[e] * wi.x; ai.y += ka[e] * wi.y; ai.z += ka[e] * wi.z; ai.w += ka[e] * wi.w;
            af.x += ka[e] * wf.x; af.y += ka[e] * wf.y; af.z += ka[e] * wf.z; af.w += ka[e] * wf.w;
        }
#pragma unroll
        for (int e = 0; e < 4; e++) {
            float4 wi = WiV[4096 + ch0 + e], wf = WfV[4096 + ch0 + e];
            ai.x += va[e] * wi.x; ai.y += va[e] * wi.y; ai.z += va[e] * wi.z; ai.w += va[e] * wi.w;
            af.x += va[e] * wf.x; af.y += va[e] * wf.y; af.z += va[e] * wf.z; af.w += va[e] * wf.w;
        }
    }

    __shared__ float4 sai[16], saf[16];
    __shared__ float sfp[4], sip[4], smn[4];
    __shared__ float dred[16];

    ai = warpsum4(ai); af = warpsum4(af);
    if (lane == 0) { sai[wid] = ai; saf[wid] = af; }
    __syncthreads();

    if (nb < 4) {
        int h = nb;
        float ti = 0.f, tf = 0.f;
#pragma unroll
        for (int w = 0; w < 16; w++) {
            float4 a = sai[w], f = saf[w];
            ti += (h == 0) ? a.x : (h == 1) ? a.y : (h == 2) ? a.z : a.w;
            tf += (h == 0) ? f.x : (h == 1) ? f.y : (h == 2) ? f.z : f.w;
        }
        float it = ti + bi[h];
        float ft = tf + bf[h];
        float logf_ = -(fmaxf(-ft, 0.f) + log1pf(expf(-fabsf(ft))));
        float mold = mst[b * 4 + h];
        float mnew = fmaxf(logf_ + mold, it);
        float ip = expf(it - mnew);
        float fp = expf(logf_ + mold - mnew);
        out[OUT_M + b * 4 + h] = mnew;
        g_fp[b * 4 + h] = fp; g_ip[b * 4 + h] = ip;
        sfp[h] = fp; sip[h] = ip; smn[h] = mnew;
    }
    __syncthreads();

    // ---- n_new, den partial; zero g_nom slice ----
    const int h = nb >> 7;                    // 128 threads per head
    float fp = sfp[h], ip = sip[h];
    float4 nold = *(const float4*)&nst[b * 2048 + ch0];
    float4 nn;
    nn.x = fp * nold.x + ip * KSC * k4.x;
    nn.y = fp * nold.y + ip * KSC * k4.y;
    nn.z = fp * nold.z + ip * KSC * k4.z;
    nn.w = fp * nold.w + ip * KSC * k4.w;
    *(float4*)&(out + OUT_N)[b * 2048 + ch0] = nn;
    *(float4*)&g_nom[b * 2048 + ch0] = make_float4(0, 0, 0, 0);

    float dacc = q4.x * nn.x + q4.y * nn.y + q4.z * nn.z + q4.w * nn.w;
    dacc = warpsum(dacc);
    if (lane == 0) dred[wid] = dacc;
    __syncthreads();
    if (nb < 4) {
        float ssum = dred[nb * 4] + dred[nb * 4 + 1] + dred[nb * 4 + 2] + dred[nb * 4 + 3];
        float den = fmaxf(fabsf(ssum), expf(-smn[nb])) + EPS_;
        g_den[b * 4 + nb] = den;
    }
}

// ============================================================
// K3: C_new = fp*C + ip*kh (x) vh fused with nom = q^T C_new,
// PLUS last-block-per-bh does the layernorm epilogue (g_h).
// grid (16, 256), block 256.
// ============================================================
__global__ void __launch_bounds__(256) cupdate_kernel(
        const float* __restrict__ Cin,
        const float* __restrict__ norm_scale, const float* __restrict__ skip,
        float* __restrict__ out) {
    int bh = blockIdx.y;
    int b = bh >> 2, h = bh & 3;
    int tid = threadIdx.x;
    int ty = tid >> 7;
    int tx = tid & 127;
    int e0 = tx * 4;
    int d0 = blockIdx.x * 32 + ty * 16;

    float fp = g_fp[bh], ip = g_ip[bh];

    __shared__ float sa[2][16], sq[2][16];
    if (tx < 16) {
        int gd = b * 2048 + h * 512 + d0 + tx;
        sa[ty][tx] = ip * KSC * g_k[gd];
        sq[ty][tx] = g_q[gd];
    }
    __syncthreads();

    float4 vh = *(const float4*)&g_v[b * 2048 + h * 512 + e0];

    const float* cbase = Cin + ((size_t)bh * 512 + d0) * 512 + e0;
    float* obase = out + OUT_C + ((size_t)bh * 512 + d0) * 512 + e0;

    float4 nom = make_float4(0.f, 0.f, 0.f, 0.f);
#pragma unroll
    for (int dd = 0; dd < 16; dd++) {
        float a  = sa[ty][dd];
        float qd = sq[ty][dd];
        float4 c = *(const float4*)(cbase + (size_t)dd * 512);
        float4 cn;
        cn.x = fp * c.x + a * vh.x;
        cn.y = fp * c.y + a * vh.y;
        cn.z = fp * c.z + a * vh.z;
        cn.w = fp * c.w + a * vh.w;
        *(float4*)(obase + (size_t)dd * 512) = cn;
        nom.x += qd * cn.x;
        nom.y += qd * cn.y;
        nom.z += qd * cn.z;
        nom.w += qd * cn.w;
    }
    float* np = &g_nom[bh * 512 + e0];
    atomicAdd(np + 0, nom.x);
    atomicAdd(np + 1, nom.y);
    atomicAdd(np + 2, nom.z);
    atomicAdd(np + 3, nom.w);

    // ---- ticket: last block for this bh runs the epilogue ----
    __threadfence();
    __shared__ unsigned slast;
    if (tid == 0) slast = atomicAdd(&g_cnt[bh], 1u);
    __syncthreads();
    if (slast != 15u) return;

    // epilogue: h_tilde = nom/den, layernorm, skip, silu(z) gate
    int lane = tid & 31, wid = tid >> 5;
    float den = g_den[bh];
    float v0 = __ldcg(&g_nom[bh * 512 + tid]) / den;
    float v1 = __ldcg(&g_nom[bh * 512 + tid + 256]) / den;

    float sm = v0 + v1;
    float ssq = v0 * v0 + v1 * v1;
    sm = warpsum(sm); ssq = warpsum(ssq);
    __shared__ float r1[8], r2[8], st[2];
    if (lane == 0) { r1[wid] = sm; r2[wid] = ssq; }
    __syncthreads();
    if (tid == 0) {
        float ts = 0.f, tss = 0.f;
#pragma unroll
        for (int w = 0; w < 8; w++) { ts += r1[w]; tss += r2[w]; }
        float mu = ts / 512.f;
        float var = tss / 512.f - mu * mu;
        st[0] = mu;
        st[1] = rsqrtf(var + EPS_);
    }
    __syncthreads();
    float mu = st[0], rstd = st[1];

#pragma unroll
    for (int i = 0; i < 2; i++) {
        int e = tid + i * 256;
        int hid = h * 512 + e;
        float v = (i == 0) ? v0 : v1;
        float hn = (v - mu) * rstd * norm_scale[h * 512 + e];
        float hv = hn + skip[hid] * g_convact[b * 2048 + hid];
        int zi = b * 4096 + 2048 + hid;
        float z = 0.f;
#pragma unroll
        for (int p = 0; p < NUP; p++) z += g_upp[p][zi];
        g_h[b * 2048 + hid] = hv * siluf(z);
    }
}

// ============================================================
// K4: y = g_h @ W_down (64x2048x1024), split-K=16, atomics.
// grid (16, 16), block 256.
// ============================================================
__global__ void __launch_bounds__(256) gemm_down_kernel(
        const float* __restrict__ Wd, float* __restrict__ out) {
    const float* A = g_h;
    const int K = HID_, N = F_, KC = 128;
    const int n0 = blockIdx.x * 64;
    const int k0 = blockIdx.y * KC;
    const int tid = threadIdx.x;
    const int tx = tid & 15, ty = tid >> 4;
    __shared__ float As[16][65];
    __shared__ float Bs[16][64];
    float acc[4][4] = {};
    for (int kt = 0; kt < KC; kt += 16) {
        __syncthreads();
#pragma unroll
        for (int i = 0; i < 4; i++) {
            int lin = tid + i * 256;
            int mm = lin >> 4, kk = lin & 15;
            As[kk][mm] = A[mm * K + k0 + kt + kk];
            int kk2 = lin >> 6, jj = lin & 63;
            Bs[kk2][jj] = Wd[(size_t)(k0 + kt + kk2) * N + n0 + jj];
        }
        __syncthreads();
#pragma unroll
        for (int kk = 0; kk < 16; kk++) {
            float4 b4 = *(const float4*)&Bs[kk][tx * 4];
            float a0 = As[kk][ty * 4 + 0];
            float a1 = As[kk][ty * 4 + 1];
            float a2 = As[kk][ty * 4 + 2];
            float a3 = As[kk][ty * 4 + 3];
            acc[0][0] += a0 * b4.x; acc[0][1] += a0 * b4.y; acc[0][2] += a0 * b4.z; acc[0][3] += a0 * b4.w;
            acc[1][0] += a1 * b4.x; acc[1][1] += a1 * b4.y; acc[1][2] += a1 * b4.z; acc[1][3] += a1 * b4.w;
            acc[2][0] += a2 * b4.x; acc[2][1] += a2 * b4.y; acc[2][2] += a2 * b4.z; acc[2][3] += a2 * b4.w;
            acc[3][0] += a3 * b4.x; acc[3][1] += a3 * b4.y; acc[3][2] += a3 * b4.z; acc[3][3] += a3 * b4.w;
        }
    }
#pragma unroll
    for (int i = 0; i < 4; i++) {
        float* crow = out + OUT_Y + (size_t)(ty * 4 + i) * N + n0 + tx * 4;
        atomicAdd(crow + 0, acc[i][0]);
        atomicAdd(crow + 1, acc[i][1]);
        atomicAdd(crow + 2, acc[i][2]);
        atomicAdd(crow + 3, acc[i][3]);
    }
}

extern "C" void kernel_launch(void* const* d_in, const int* in_sizes, int n_in,
                              void* d_out, int out_size) {
    const float* inputs     = (const float*)d_in[0];
    const float* C          = (const float*)d_in[1];
    const float* n_state    = (const float*)d_in[2];
    const float* m_state    = (const float*)d_in[3];
    const float* conv_state = (const float*)d_in[4];
    const float* W_up       = (const float*)d_in[5];
    const float* conv_w     = (const float*)d_in[6];
    const float* conv_b     = (const float*)d_in[7];
    const float* Wq         = (const float*)d_in[8];
    const float* Wk         = (const float*)d_in[9];
    const float* Wv         = (const float*)d_in[10];
    const float* Wi         = (const float*)d_in[11];
    const float* bi         = (const float*)d_in[12];
    const float* Wf         = (const float*)d_in[13];
    const float* bf         = (const float*)d_in[14];
    const float* norm_scale = (const float*)d_in[15];
    const float* skip       = (const float*)d_in[16];
    const float* W_down     = (const float*)d_in[17];
    float* out = (float*)d_out;

    // K1: up = inputs @ W_up (64x1024x4096), split-K=8, partial buffers
    gemm_up_kernel<<<dim3(64, 8), 256>>>(inputs, W_up);

    // K2: fused conv/qkv/gates/n_new/den (+zero y, counters, nom)
    fused_mid_kernel<<<64, 512>>>(conv_state, conv_w, conv_b, Wq, Wk, Wv,
                                  n_state, m_state, Wi, bi, Wf, bf, out);

    // K3: C update + q^T C_new + fused layernorm epilogue (last block per bh)
    cupdate_kernel<<<dim3(16, 256), 256>>>(C, norm_scale, skip, out);

    // K4: down projection, split-K=16
    gemm_down_kernel<<<dim3(16, 16), 256>>>(W_down, out);
}